// round 8
// baseline (speedup 1.0000x reference)
#include <cuda_runtime.h>
#include <cuda_bf16.h>
#include <cstdint>

// LinearUnit single-step LRU cell (elementwise, HBM-bound):
//   out[b, j] = state[b, j] * a_diag[j] + (in[b,0]+in[b,1]) * b_col[j]
// BATCH=4096, NUM_UNITS=8192 (=2S), S=4096. Output = (y, y) duplicated.
// Traffic floor: 128MB state read + 256MB write = 384MB. Measured memory
// plateau ~5.9 TB/s for this 1:2 read:write mix (R5/R7). This round: R5's
// best config (ITEMS=2) with default write-back stores instead of __stcs.

static constexpr int BATCH     = 4096;
static constexpr int NUM_UNITS = 8192;
static constexpr int S         = NUM_UNITS / 2;
static constexpr int NU4       = NUM_UNITS / 4;   // 2048 float4 per row
static constexpr int S4        = S / 4;           // 1024
static constexpr int TOTAL4    = BATCH * NU4;     // 8,388,608 (fits int32)

static constexpr int THREADS        = 256;
static constexpr int ITEMS          = 2;
static constexpr int F4_PER_BLOCK   = THREADS * ITEMS;        // 512
static constexpr int BLOCKS_PER_ROW = NU4 / F4_PER_BLOCK;     // 4
static constexpr int GRID           = BATCH * BLOCKS_PER_ROW; // 16384

template <int DUP>
__global__ __launch_bounds__(THREADS)
void lru_cell_kernel(const float* __restrict__ inputs,    // (B, 2)
                     const float* __restrict__ state,     // (B, NU)
                     const float* __restrict__ as_real,   // (NU,)
                     const float* __restrict__ as_imag,   // (NU,)
                     const float* __restrict__ bs_real,   // (NU,)
                     const float* __restrict__ bs_imag,   // (NU,)
                     float* __restrict__ out)
{
    const float4* state4   = reinterpret_cast<const float4*>(state);
    const float4* as_real4 = reinterpret_cast<const float4*>(as_real);
    const float4* as_imag4 = reinterpret_cast<const float4*>(as_imag);
    const float4* bs_real4 = reinterpret_cast<const float4*>(bs_real);
    const float4* bs_imag4 = reinterpret_cast<const float4*>(bs_imag);
    float4*       out4     = reinterpret_cast<float4*>(out);

    const int blk = blockIdx.x;
    const int b   = blk >> 2;                     // row (block-uniform)
    const int j4b = (blk & 3) * F4_PER_BLOCK;     // row-local float4 offset

    // Per-row input sum: one 8B load, L2-resident, block-uniform value.
    const float2 in2 = __ldg(reinterpret_cast<const float2*>(inputs) + b);
    const float  u   = in2.x + in2.y;

    // Block sits entirely in one param half (512 | 1024) -> uniform select.
    const float4* ap;
    const float4* cp;
    if (j4b < S4) { ap = as_real4;       cp = bs_real4; }
    else          { ap = as_imag4 - S4;  cp = bs_imag4 - S4; }

    const int j4_0 = j4b + threadIdx.x;
    const int base = b * NU4;

    const int idx0 = base + j4_0;
    const int idx1 = idx0 + THREADS;
    // Streaming reads (touch-once; keep L2 for params + write buffering).
    float4 s0 = __ldcs(state4 + idx0);
    float4 s1 = __ldcs(state4 + idx1);

    float4 a0 = __ldg(ap + j4_0);
    float4 c0 = __ldg(cp + j4_0);
    float4 a1 = __ldg(ap + j4_0 + THREADS);
    float4 c1 = __ldg(cp + j4_0 + THREADS);

    float4 r0, r1;
    r0.x = fmaf(s0.x, a0.x, u * c0.x);
    r0.y = fmaf(s0.y, a0.y, u * c0.y);
    r0.z = fmaf(s0.z, a0.z, u * c0.z);
    r0.w = fmaf(s0.w, a0.w, u * c0.w);
    r1.x = fmaf(s1.x, a1.x, u * c1.x);
    r1.y = fmaf(s1.y, a1.y, u * c1.y);
    r1.z = fmaf(s1.z, a1.z, u * c1.z);
    r1.w = fmaf(s1.w, a1.w, u * c1.w);

    // Default write-back stores: let L2 buffer/coalesce the write stream
    // before the DRAM drain (vs evict-first __stcs).
    out4[idx0] = r0;
    out4[idx1] = r1;
    if (DUP) {
        out4[idx0 + TOTAL4] = r0;
        out4[idx1 + TOTAL4] = r1;
    }
}

extern "C" void kernel_launch(void* const* d_in, const int* in_sizes, int n_in,
                              void* d_out, int out_size) {
    const float* inputs  = (const float*)d_in[0];
    const float* state   = (const float*)d_in[1];
    const float* as_real = (const float*)d_in[2];
    const float* as_imag = (const float*)d_in[3];
    const float* bs_real = (const float*)d_in[4];
    const float* bs_imag = (const float*)d_in[5];
    float* out = (float*)d_out;

    const long long total = (long long)BATCH * NUM_UNITS;
    if ((long long)out_size >= 2 * total) {
        lru_cell_kernel<1><<<GRID, THREADS>>>(inputs, state, as_real, as_imag,
                                              bs_real, bs_imag, out);
    } else {
        lru_cell_kernel<0><<<GRID, THREADS>>>(inputs, state, as_real, as_imag,
                                              bs_real, bs_imag, out);
    }
}

// round 9
// speedup vs baseline: 1.0045x; 1.0045x over previous
#include <cuda_runtime.h>
#include <cuda_bf16.h>
#include <cstdint>

// LinearUnit single-step LRU cell (elementwise, HBM-bound):
//   out[b, j] = state[b, j] * a_diag[j] + (in[b,0]+in[b,1]) * b_col[j]
// BATCH=4096, NUM_UNITS=8192 (=2S), S=4096. Output = (y, y) duplicated.
// Traffic floor: 128MB state read + 256MB write = 384MB.
// Measured plateau (R5/R7/R8): ~5.85-5.9 TB/s regardless of MLP / store
// policy. This round: per-stream store policy — copy 1 write-back (L2
// buffered), copy 2 write-through (no L2 fill; pure sink stream).

static constexpr int BATCH     = 4096;
static constexpr int NUM_UNITS = 8192;
static constexpr int S         = NUM_UNITS / 2;
static constexpr int NU4       = NUM_UNITS / 4;   // 2048 float4 per row
static constexpr int S4        = S / 4;           // 1024
static constexpr int TOTAL4    = BATCH * NU4;     // 8,388,608 (fits int32)

static constexpr int THREADS        = 256;
static constexpr int ITEMS          = 2;
static constexpr int F4_PER_BLOCK   = THREADS * ITEMS;        // 512
static constexpr int BLOCKS_PER_ROW = NU4 / F4_PER_BLOCK;     // 4
static constexpr int GRID           = BATCH * BLOCKS_PER_ROW; // 16384

template <int DUP>
__global__ __launch_bounds__(THREADS)
void lru_cell_kernel(const float* __restrict__ inputs,    // (B, 2)
                     const float* __restrict__ state,     // (B, NU)
                     const float* __restrict__ as_real,   // (NU,)
                     const float* __restrict__ as_imag,   // (NU,)
                     const float* __restrict__ bs_real,   // (NU,)
                     const float* __restrict__ bs_imag,   // (NU,)
                     float* __restrict__ out)
{
    const float4* state4   = reinterpret_cast<const float4*>(state);
    const float4* as_real4 = reinterpret_cast<const float4*>(as_real);
    const float4* as_imag4 = reinterpret_cast<const float4*>(as_imag);
    const float4* bs_real4 = reinterpret_cast<const float4*>(bs_real);
    const float4* bs_imag4 = reinterpret_cast<const float4*>(bs_imag);
    float4*       out4     = reinterpret_cast<float4*>(out);

    const int blk = blockIdx.x;
    const int b   = blk >> 2;                     // row (block-uniform)
    const int j4b = (blk & 3) * F4_PER_BLOCK;     // row-local float4 offset

    // Per-row input sum: one 8B load, L2-resident, block-uniform value.
    const float2 in2 = __ldg(reinterpret_cast<const float2*>(inputs) + b);
    const float  u   = in2.x + in2.y;

    // Block sits entirely in one param half (512 | 1024) -> uniform select.
    const float4* ap;
    const float4* cp;
    if (j4b < S4) { ap = as_real4;       cp = bs_real4; }
    else          { ap = as_imag4 - S4;  cp = bs_imag4 - S4; }

    const int j4_0 = j4b + threadIdx.x;
    const int base = b * NU4;

    const int idx0 = base + j4_0;
    const int idx1 = idx0 + THREADS;
    // Streaming reads (touch-once; keep L2 for params + write buffering).
    float4 s0 = __ldcs(state4 + idx0);
    float4 s1 = __ldcs(state4 + idx1);

    float4 a0 = __ldg(ap + j4_0);
    float4 c0 = __ldg(cp + j4_0);
    float4 a1 = __ldg(ap + j4_0 + THREADS);
    float4 c1 = __ldg(cp + j4_0 + THREADS);

    float4 r0, r1;
    r0.x = fmaf(s0.x, a0.x, u * c0.x);
    r0.y = fmaf(s0.y, a0.y, u * c0.y);
    r0.z = fmaf(s0.z, a0.z, u * c0.z);
    r0.w = fmaf(s0.w, a0.w, u * c0.w);
    r1.x = fmaf(s1.x, a1.x, u * c1.x);
    r1.y = fmaf(s1.y, a1.y, u * c1.y);
    r1.z = fmaf(s1.z, a1.z, u * c1.z);
    r1.w = fmaf(s1.w, a1.w, u * c1.w);

    // Copy 1: default write-back (L2-buffered burst toward DRAM).
    out4[idx0] = r0;
    out4[idx1] = r1;
    if (DUP) {
        // Copy 2: write-through — pure sink stream, don't claim L2 lines.
        __stwt(out4 + idx0 + TOTAL4, r0);
        __stwt(out4 + idx1 + TOTAL4, r1);
    }
}

extern "C" void kernel_launch(void* const* d_in, const int* in_sizes, int n_in,
                              void* d_out, int out_size) {
    const float* inputs  = (const float*)d_in[0];
    const float* state   = (const float*)d_in[1];
    const float* as_real = (const float*)d_in[2];
    const float* as_imag = (const float*)d_in[3];
    const float* bs_real = (const float*)d_in[4];
    const float* bs_imag = (const float*)d_in[5];
    float* out = (float*)d_out;

    const long long total = (long long)BATCH * NUM_UNITS;
    if ((long long)out_size >= 2 * total) {
        lru_cell_kernel<1><<<GRID, THREADS>>>(inputs, state, as_real, as_imag,
                                              bs_real, bs_imag, out);
    } else {
        lru_cell_kernel<0><<<GRID, THREADS>>>(inputs, state, as_real, as_imag,
                                              bs_real, bs_imag, out);
    }
}